// round 5
// baseline (speedup 1.0000x reference)
#include <cuda_runtime.h>
#include <cuda_bf16.h>
#include <stdint.h>

// ---------------------------------------------------------------------------
// Device-global scratch. Two *separate* digit arrays (no offset arithmetic).
// Layout: [64 cols][COLP bytes] s8, column o contiguous in k, padded to 528.
// ---------------------------------------------------------------------------
#define COLP 528
#define DIGSZ (64 * COLP)            // 33792
static __device__ __align__(16) signed char g_Wd1[DIGSZ];
static __device__ __align__(16) signed char g_Wd2[DIGSZ];
static __device__ float g_corr[64];  // sum_k W[k][o] / 255
static __device__ float g_sc1, g_sc2;
static __device__ int   g_stride;    // u32 words per x element: 1 (int32) or 2 (int64)

// ---------------------------------------------------------------------------
// IMMA m16n8k32 s8*s8 -> s32
// ---------------------------------------------------------------------------
__device__ __forceinline__ void imma(int* c, uint32_t a0, uint32_t a1,
                                     uint32_t a2, uint32_t a3,
                                     uint32_t b0, uint32_t b1) {
    asm volatile(
        "mma.sync.aligned.m16n8k32.row.col.s32.s8.s8.s32 "
        "{%0,%1,%2,%3}, {%4,%5,%6,%7}, {%8,%9}, {%0,%1,%2,%3};"
        : "+r"(c[0]), "+r"(c[1]), "+r"(c[2]), "+r"(c[3])
        : "r"(a0), "r"(a1), "r"(a2), "r"(a3), "r"(b0), "r"(b1));
}

// ---------------------------------------------------------------------------
// Prep: detect x width; quantize W twice (coarse + residual); column sums.
// ---------------------------------------------------------------------------
static __global__ void bf_prep(const float* __restrict__ W,
                               const uint32_t* __restrict__ xw)
{
    __shared__ float red[512];
    __shared__ float part[8][64];
    int t = threadIdx.x;

    if (t == 0) {
        uint32_t acc = 0;
        for (int j = 1; j < 256; j += 2) acc |= xw[j];
        g_stride = (acc == 0u) ? 2 : 1;
    }

    float mx = 0.f;
    for (int i = t; i < 496 * 64; i += 512) mx = fmaxf(mx, fabsf(W[i]));
    red[t] = mx;
    __syncthreads();
    for (int d = 256; d > 0; d >>= 1) {
        if (t < d) red[t] = fmaxf(red[t], red[t + d]);
        __syncthreads();
    }
    float maxabs = fmaxf(red[0], 1e-30f);
    float s1 = maxabs * (1.0f / 127.0f);
    float inv1 = 127.0f / maxabs;
    float s2 = s1 * (1.0f / 254.0f);
    float inv2 = 254.0f / s1;

    for (int idx = t; idx < 64 * 512; idx += 512) {
        int k = idx >> 6, o = idx & 63;
        float w = (k < 496) ? W[k * 64 + o] : 0.f;
        int d1 = __float2int_rn(w * inv1);
        d1 = max(-127, min(127, d1));
        float r = w - s1 * (float)d1;
        int d2 = __float2int_rn(r * inv2);
        d2 = max(-127, min(127, d2));
        g_Wd1[o * COLP + k] = (signed char)d1;
        g_Wd2[o * COLP + k] = (signed char)d2;
    }

    {
        int o = t & 63, sl = t >> 6;
        float cs = 0.f;
        for (int k = sl; k < 496; k += 8) cs += W[k * 64 + o];
        part[sl][o] = cs;
    }
    __syncthreads();
    if (t < 64) {
        float s = 0.f;
        for (int k = 0; k < 8; k++) s += part[k][t];
        g_corr[t] = s * (1.0f / 255.0f);
        if (t == 0) {
            g_sc1 = (2.0f / 255.0f) * s1;
            g_sc2 = (2.0f / 255.0f) * s2;
        }
    }
}

// ---------------------------------------------------------------------------
// Main persistent kernel.
// SMEM: sA [0,67584) | sB1 [67584,101376) | sB2 [101376,135168)
//       bw [135168,135712) 136 u32 | corr [135712,135968)
// ---------------------------------------------------------------------------
#define A_OFF    0
#define B1_OFF   67584
#define B2_OFF   101376
#define BW_OFF   135168
#define CORR_OFF 135712
#define SMEM_DYN 135968

static __global__ void __launch_bounds__(512, 1)
bf_main(const uint32_t* __restrict__ xw, float* __restrict__ out)
{
    extern __shared__ __align__(16) char sm[];
    char*          sA    = sm + A_OFF;
    uint32_t*      bw    = (uint32_t*)(sm + BW_OFF);
    unsigned char* bbyte = (unsigned char*)bw;
    float*         scorr = (float*)(sm + CORR_OFF);

    int t = threadIdx.x, lane = t & 31, wid = t >> 5;

    // One-time: copy W digits into SMEM, corr, zero byte-pad words
    {
        const uint4* s1p = (const uint4*)g_Wd1;
        const uint4* s2p = (const uint4*)g_Wd2;
        uint4* d1p = (uint4*)(sm + B1_OFF);
        uint4* d2p = (uint4*)(sm + B2_OFF);
        for (int i = t; i < 2112; i += 512) { d1p[i] = s1p[i]; d2p[i] = s2p[i]; }
        if (t < 64) scorr[t] = g_corr[t];
        if (t < 8)  bw[128 + t] = 0u;
    }
    const float sc1 = g_sc1;
    const float sc2 = g_sc2;
    const int stride = g_stride;

    // ---- per-thread invariants: A build (thread t: row t>>2, quarter t&3) ----
    const int r = t >> 2, q = t & 3;
    const int g = r >> 3, s = r & 7;
    const int g4 = g >> 2, gr = g & 3;
    const uint32_t sel0 = 0x3210u + 0x1111u * (uint32_t)gr;
    const uint32_t sel1 = sel0 + 0x1111u;
    const uint32_t M1 = 0x01010101u * ((0xFFu << s) & 0xFFu);
    const uint32_t M2 = 0x01010101u * (0xFFu >> (8 - s));

    // ---- per-thread invariants: MMA (warp = m-block x n-half) ----
    const int mb = wid >> 1;            // 16-row m-block
    const int nh = wid & 1;             // 32-col n-half
    const int rb = mb * 16;
    const int gid = lane >> 2, tig = lane & 3;
    const char* aRow0 = sA + (rb + gid) * COLP + 4 * tig;
    const int colbase = nh * 32;
    const int bColOff = (colbase + gid) * COLP + 4 * tig;
    const char* bp1 = sm + B1_OFF + bColOff;
    const char* bp2 = sm + B2_OFF + bColOff;
    const int row0 = rb + gid;

    __syncthreads();

    // epilogue constants (after sync: scorr ready)
    float corr0[4], corr1[4];
    #pragma unroll
    for (int nt = 0; nt < 4; nt++) {
        int col = colbase + nt * 8 + 2 * tig;
        corr0[nt] = scorr[col];
        corr1[nt] = scorr[col + 1];
    }

    for (int n = blockIdx.x; n < 2048; n += 148) {
        // ---- load 512 input bytes ----
        bbyte[t] = (unsigned char)xw[((size_t)n * 512 + t) * (size_t)stride];
        __syncthreads();

        // ---- build A: centered sliding-window bytes ----
        {
            char* rowp = sA + r * COLP + q * 128;
            #pragma unroll
            for (int m = 0; m < 8; m++) {
                int wbase = q * 32 + m * 4;
                uint32_t A0 = bw[wbase + g4];
                uint32_t acc[4];
                #pragma unroll
                for (int j = 0; j < 4; j++) {
                    uint32_t B0 = bw[wbase + g4 + j + 1];
                    uint32_t X = __byte_perm(A0, B0, sel0);
                    uint32_t Y = __byte_perm(A0, B0, sel1);
                    acc[j] = (((X << s) & M1) | ((Y >> (8 - s)) & M2)) ^ 0x80808080u;
                    A0 = B0;
                }
                *(uint4*)(rowp + m * 16) = make_uint4(acc[0], acc[1], acc[2], acc[3]);
            }
        }
        __syncthreads();

        // ---- MMA: both digits in one k-loop, separate accumulators ----
        int c1[16], c2[16];
        #pragma unroll
        for (int i = 0; i < 16; i++) { c1[i] = 0; c2[i] = 0; }

        #pragma unroll
        for (int k0 = 0; k0 < 512; k0 += 32) {
            uint32_t a0 = *(const uint32_t*)(aRow0 + k0);
            uint32_t a2 = *(const uint32_t*)(aRow0 + k0 + 16);
            uint32_t a1 = *(const uint32_t*)(aRow0 + 8 * COLP + k0);
            uint32_t a3 = *(const uint32_t*)(aRow0 + 8 * COLP + k0 + 16);
            #pragma unroll
            for (int nt = 0; nt < 4; nt++) {
                const char* q1 = bp1 + nt * (8 * COLP) + k0;
                uint32_t b0 = *(const uint32_t*)(q1);
                uint32_t b1 = *(const uint32_t*)(q1 + 16);
                imma(c1 + 4 * nt, a0, a1, a2, a3, b0, b1);
                const char* q2 = bp2 + nt * (8 * COLP) + k0;
                uint32_t e0 = *(const uint32_t*)(q2);
                uint32_t e1 = *(const uint32_t*)(q2 + 16);
                imma(c2 + 4 * nt, a0, a1, a2, a3, e0, e1);
            }
        }

        // ---- epilogue: out = sc1*C1 + sc2*C2 + corr (all exact FMAs) ----
        {
            float* po = out + (size_t)n * 8192;   // 128*64 per tile
            #pragma unroll
            for (int nt = 0; nt < 4; nt++) {
                int col = colbase + nt * 8 + 2 * tig;
                float2 v0, v1;
                v0.x = fmaf(sc1, (float)c1[4*nt+0], fmaf(sc2, (float)c2[4*nt+0], corr0[nt]));
                v0.y = fmaf(sc1, (float)c1[4*nt+1], fmaf(sc2, (float)c2[4*nt+1], corr1[nt]));
                v1.x = fmaf(sc1, (float)c1[4*nt+2], fmaf(sc2, (float)c2[4*nt+2], corr0[nt]));
                v1.y = fmaf(sc1, (float)c1[4*nt+3], fmaf(sc2, (float)c2[4*nt+3], corr1[nt]));
                __stcs((float2*)(po + row0 * 64 + col), v0);
                __stcs((float2*)(po + (row0 + 8) * 64 + col), v1);
            }
        }
        __syncthreads();   // protect sA/bw before next tile overwrites
    }
}

// ---------------------------------------------------------------------------
extern "C" void kernel_launch(void* const* d_in, const int* in_sizes, int n_in,
                              void* d_out, int out_size)
{
    const uint32_t* xw  = (const uint32_t*)d_in[0];
    const float*    W   = (const float*)d_in[1];
    float*          out = (float*)d_out;

    cudaFuncSetAttribute(bf_main, cudaFuncAttributeMaxDynamicSharedMemorySize, SMEM_DYN);
    bf_prep<<<1, 512>>>(W, xw);
    bf_main<<<148, 512, SMEM_DYN>>>(xw, out);
}

// round 6
// speedup vs baseline: 1.2747x; 1.2747x over previous
#include <cuda_runtime.h>
#include <stdint.h>

#define COLA 528                 // A row pad (bytes)
#define COLB 544                 // B col pad (bank-conflict-free LDS.64)
#define ASZ (128 * COLA)         // 67584
#define BSZ (64 * COLB)          // 34816

static __device__ __align__(16) signed char g_Wd1[BSZ];
static __device__ __align__(16) signed char g_Wd2[BSZ];
static __device__ float g_corr[64];
static __device__ float g_sc1, g_sc2;
static __device__ int   g_stride;     // u32 words per x element (1=int32, 2=int64)
static __device__ int   g_maxbits;    // float bits of max|W| (>=0); idempotent across replays

// ---------------------------------------------------------------------------
__device__ __forceinline__ void imma(int* c, uint32_t a0, uint32_t a1,
                                     uint32_t a2, uint32_t a3,
                                     uint32_t b0, uint32_t b1) {
    asm volatile(
        "mma.sync.aligned.m16n8k32.row.col.s32.s8.s8.s32 "
        "{%0,%1,%2,%3}, {%4,%5,%6,%7}, {%8,%9}, {%0,%1,%2,%3};"
        : "+r"(c[0]), "+r"(c[1]), "+r"(c[2]), "+r"(c[3])
        : "r"(a0), "r"(a1), "r"(a2), "r"(a3), "r"(b0), "r"(b1));
}

// ---------------------------------------------------------------------------
// Prep 1: global max|W| (grid 32 x 256) + input width detection.
// ---------------------------------------------------------------------------
static __global__ void bf_prep1(const float* __restrict__ W,
                                const uint32_t* __restrict__ xw)
{
    if (blockIdx.x == 0 && threadIdx.x == 0) {
        uint32_t acc = 0;
        for (int j = 1; j < 256; j += 2) acc |= xw[j];
        g_stride = (acc == 0u) ? 2 : 1;
    }
    int t = blockIdx.x * 256 + threadIdx.x;
    float mx = 0.f;
    for (int i = t; i < 496 * 64; i += 32 * 256) mx = fmaxf(mx, fabsf(W[i]));
    #pragma unroll
    for (int o = 16; o; o >>= 1) mx = fmaxf(mx, __shfl_xor_sync(0xFFFFFFFFu, mx, o));
    if ((threadIdx.x & 31) == 0) atomicMax(&g_maxbits, __float_as_int(mx));
}

// ---------------------------------------------------------------------------
// Prep 2: quantize W into two s8 digits directly in MMA fragment order
// (col o: [ks][tig][half] 8-byte groups), column sums. Grid 64 x 512.
// ---------------------------------------------------------------------------
static __global__ void bf_prep2(const float* __restrict__ W)
{
    __shared__ float red[512];
    int o = blockIdx.x;
    int k = threadIdx.x;

    float maxabs = fmaxf(__int_as_float(g_maxbits), 1e-30f);
    float s1 = maxabs * (1.0f / 127.0f), inv1 = 127.0f / maxabs;
    float s2 = s1 * (1.0f / 254.0f),     inv2 = 254.0f / s1;

    float w = (k < 496) ? W[k * 64 + o] : 0.f;
    int d1 = __float2int_rn(w * inv1);
    d1 = max(-127, min(127, d1));
    float r = w - s1 * (float)d1;
    int d2 = __float2int_rn(r * inv2);
    d2 = max(-127, min(127, d2));

    int ks = k >> 5, wrd = (k >> 2) & 7, tig = wrd & 3, half = wrd >> 2, byt = k & 3;
    int addr = o * COLB + ks * 32 + tig * 8 + half * 4 + byt;
    g_Wd1[addr] = (signed char)d1;
    g_Wd2[addr] = (signed char)d2;

    red[k] = w;
    __syncthreads();
    for (int d = 256; d; d >>= 1) {
        if (k < d) red[k] += red[k + d];
        __syncthreads();
    }
    if (k == 0) {
        g_corr[o] = red[0] * (1.0f / 255.0f);
        if (o == 0) {
            g_sc1 = (2.0f / 255.0f) * s1;
            g_sc2 = (2.0f / 255.0f) * s2;
        }
    }
}

// ---------------------------------------------------------------------------
// Main persistent kernel, software-pipelined with double-buffered A.
// SMEM: sA0 | sA1 | B1 | B2 | bw0 | bw1 | corr
// ---------------------------------------------------------------------------
#define SMEM_DYN (2 * ASZ + 2 * BSZ + 2 * 544 + 256)   // 206144

__device__ __forceinline__ void buildA(const uint32_t* __restrict__ bw, char* rowp,
                                       int q, int g4, uint32_t sel0, uint32_t sel1,
                                       uint32_t M1, uint32_t M2, int s)
{
    #pragma unroll
    for (int m = 0; m < 8; m++) {
        int wbase = q * 32 + m * 4;
        uint32_t A0 = bw[wbase + g4];
        uint32_t acc[4];
        #pragma unroll
        for (int j = 0; j < 4; j++) {
            uint32_t B0 = bw[wbase + g4 + j + 1];
            uint32_t X = __byte_perm(A0, B0, sel0);
            uint32_t Y = __byte_perm(A0, B0, sel1);
            acc[j] = (((X << s) & M1) | ((Y >> (8 - s)) & M2)) ^ 0x80808080u;
            A0 = B0;
        }
        *(uint4*)(rowp + m * 16) = make_uint4(acc[0], acc[1], acc[2], acc[3]);
    }
}

static __global__ void __launch_bounds__(512, 1)
bf_main(const uint32_t* __restrict__ xw, float* __restrict__ out)
{
    extern __shared__ __align__(16) char sm[];
    char* sA0 = sm;
    char* sA1 = sm + ASZ;
    char* sB1 = sm + 2 * ASZ;
    char* sB2 = sm + 2 * ASZ + BSZ;
    uint32_t* bw0 = (uint32_t*)(sm + 2 * ASZ + 2 * BSZ);
    uint32_t* bw1 = bw0 + 136;
    float* scorr  = (float*)(sm + 2 * ASZ + 2 * BSZ + 2 * 544);

    int t = threadIdx.x, lane = t & 31, wid = t >> 5;
    const int stride = g_stride;
    const float sc1 = g_sc1, sc2 = g_sc2;

    // ---- invariants: A build (thread -> row t>>2, quarter t&3) ----
    const int r = t >> 2, q = t & 3;
    const int g = r >> 3, s = r & 7;
    const int g4 = g >> 2, gr = g & 3;
    const uint32_t sel0 = 0x3210u + 0x1111u * (uint32_t)gr;
    const uint32_t sel1 = sel0 + 0x1111u;
    const uint32_t M1 = 0x01010101u * ((0xFFu << s) & 0xFFu);
    const uint32_t M2 = 0x01010101u * (0xFFu >> (8 - s));
    char* rowp0 = sA0 + r * COLA + q * 128;
    char* rowp1 = sA1 + r * COLA + q * 128;

    // ---- invariants: MMA (warp = 16-row m-block x 32-col n-half) ----
    const int mb = wid >> 1, nh = wid & 1;
    const int rb = mb * 16;
    const int gid = lane >> 2, tig = lane & 3;
    const int aOff = (rb + gid) * COLA + 4 * tig;
    const int colbase = nh * 32;
    const int bCol = (colbase + gid) * COLB + tig * 8;
    const int row0 = rb + gid;

    int n0 = blockIdx.x;

    // ---- prologue: bytes(n0), one-time copies, pads ----
    {
        unsigned char* bb = (unsigned char*)bw0;
        bb[t] = (unsigned char)xw[((size_t)n0 * 512 + t) * (size_t)stride];
        const uint4* w1 = (const uint4*)g_Wd1;
        const uint4* w2 = (const uint4*)g_Wd2;
        uint4* p1 = (uint4*)sB1;
        uint4* p2 = (uint4*)sB2;
        for (int i = t; i < BSZ / 16; i += 512) { p1[i] = w1[i]; p2[i] = w2[i]; }
        if (t < 64) scorr[t] = g_corr[t];
        if (t < 8)  { bw0[128 + t] = 0u; bw1[128 + t] = 0u; }
    }
    __syncthreads();

    // epilogue constants
    float corr0[4], corr1[4];
    #pragma unroll
    for (int nt = 0; nt < 4; nt++) {
        int col = colbase + nt * 8 + 2 * tig;
        corr0[nt] = scorr[col];
        corr1[nt] = scorr[col + 1];
    }

    buildA(bw0, rowp0, q, g4, sel0, sel1, M1, M2, s);
    if (n0 + 148 < 2048) {
        unsigned char* bb = (unsigned char*)bw1;
        bb[t] = (unsigned char)xw[((size_t)(n0 + 148) * 512 + t) * (size_t)stride];
    }
    __syncthreads();

    int p = 0;
    for (int n = n0; n < 2048; n += 148, p ^= 1) {
        const char* sA = p ? sA1 : sA0;

        // ---- MMA over both digits ----
        int c1[16], c2[16];
        #pragma unroll
        for (int i = 0; i < 16; i++) { c1[i] = 0; c2[i] = 0; }

        const char* aR = sA + aOff;
        #pragma unroll
        for (int ks = 0; ks < 16; ks++) {
            int k0 = ks * 32;
            uint32_t a0 = *(const uint32_t*)(aR + k0);
            uint32_t a2 = *(const uint32_t*)(aR + k0 + 16);
            uint32_t a1 = *(const uint32_t*)(aR + 8 * COLA + k0);
            uint32_t a3 = *(const uint32_t*)(aR + 8 * COLA + k0 + 16);
            #pragma unroll
            for (int nt = 0; nt < 4; nt++) {
                uint2 b = *(const uint2*)(sB1 + bCol + nt * (8 * COLB) + k0);
                imma(c1 + 4 * nt, a0, a1, a2, a3, b.x, b.y);
                uint2 e = *(const uint2*)(sB2 + bCol + nt * (8 * COLB) + k0);
                imma(c2 + 4 * nt, a0, a1, a2, a3, e.x, e.y);
            }
        }

        // ---- epilogue ----
        {
            float* po = out + (size_t)n * 8192;
            #pragma unroll
            for (int nt = 0; nt < 4; nt++) {
                int col = colbase + nt * 8 + 2 * tig;
                float2 v0, v1;
                v0.x = fmaf(sc1, (float)c1[4*nt+0], fmaf(sc2, (float)c2[4*nt+0], corr0[nt]));
                v0.y = fmaf(sc1, (float)c1[4*nt+1], fmaf(sc2, (float)c2[4*nt+1], corr1[nt]));
                v1.x = fmaf(sc1, (float)c1[4*nt+2], fmaf(sc2, (float)c2[4*nt+2], corr0[nt]));
                v1.y = fmaf(sc1, (float)c1[4*nt+3], fmaf(sc2, (float)c2[4*nt+3], corr1[nt]));
                __stcs((float2*)(po + row0 * 64 + col), v0);
                __stcs((float2*)(po + (row0 + 8) * 64 + col), v1);
            }
        }

        // ---- pipeline: build A(n+148) from the other byte buffer ----
        if (n + 148 < 2048)
            buildA(p ? bw0 : bw1, p ? rowp0 : rowp1, q, g4, sel0, sel1, M1, M2, s);

        // ---- prefetch bytes(n+296) into the buffer just consumed ----
        if (n + 296 < 2048) {
            unsigned char* bb = (unsigned char*)(p ? bw1 : bw0);
            bb[t] = (unsigned char)xw[((size_t)(n + 296) * 512 + t) * (size_t)stride];
        }
        __syncthreads();
    }
}

// ---------------------------------------------------------------------------
extern "C" void kernel_launch(void* const* d_in, const int* in_sizes, int n_in,
                              void* d_out, int out_size)
{
    const uint32_t* xw  = (const uint32_t*)d_in[0];
    const float*    W   = (const float*)d_in[1];
    float*          out = (float*)d_out;

    cudaFuncSetAttribute(bf_main, cudaFuncAttributeMaxDynamicSharedMemorySize, SMEM_DYN);
    bf_prep1<<<32, 256>>>(W, xw);
    bf_prep2<<<64, 512>>>(W);
    bf_main<<<148, 512, SMEM_DYN>>>(xw, out);
}

// round 7
// speedup vs baseline: 1.3318x; 1.0448x over previous
#include <cuda_runtime.h>
#include <stdint.h>

#define COLA 528                 // A row pad (bytes)
#define COLB 544                 // B col pad (bytes)
#define ASZ (128 * COLA)         // 67584
#define BSZ (64 * COLB)          // 34816

static __device__ __align__(16) signed char g_Wd1[BSZ];
static __device__ __align__(16) signed char g_Wd2[BSZ];
static __device__ float g_corr[64];
static __device__ float g_sc;         // (2/255) * s1 / 128
static __device__ int   g_stride;     // u32 words per x element (1=int32, 2=int64)

// ---------------------------------------------------------------------------
__device__ __forceinline__ void imma(int* c, uint32_t a0, uint32_t a1,
                                     uint32_t a2, uint32_t a3,
                                     uint32_t b0, uint32_t b1) {
    asm volatile(
        "mma.sync.aligned.m16n8k32.row.col.s32.s8.s8.s32 "
        "{%0,%1,%2,%3}, {%4,%5,%6,%7}, {%8,%9}, {%0,%1,%2,%3};"
        : "+r"(c[0]), "+r"(c[1]), "+r"(c[2]), "+r"(c[3])
        : "r"(a0), "r"(a1), "r"(a2), "r"(a3), "r"(b0), "r"(b1));
}

// ---------------------------------------------------------------------------
// Fused prep: grid 64 (block = output col o), 512 threads (thread = k).
// Each block independently computes max|W| (redundant, deterministic), then
// quantizes its column into two s8 digits (radix-128) in MMA fragment order,
// and reduces the column sum.
// ---------------------------------------------------------------------------
static __global__ void bf_prep(const float* __restrict__ W,
                               const uint32_t* __restrict__ xw)
{
    __shared__ float red[512];
    int o = blockIdx.x, k = threadIdx.x;

    if (o == 0 && k == 0) {
        uint32_t acc = 0;
        for (int j = 1; j < 256; j += 2) acc |= xw[j];
        g_stride = (acc == 0u) ? 2 : 1;
    }

    float mx = 0.f;
    for (int i = k; i < 496 * 64; i += 512) mx = fmaxf(mx, fabsf(W[i]));
    red[k] = mx;
    __syncthreads();
    for (int d = 256; d; d >>= 1) {
        if (k < d) red[k] = fmaxf(red[k], red[k + d]);
        __syncthreads();
    }
    float maxabs = fmaxf(red[0], 1e-30f);
    __syncthreads();

    float s1 = maxabs * (1.0f / 127.0f), inv1 = 127.0f / maxabs;
    float inv2 = 128.0f / s1;             // s2 = s1/128

    float w = (k < 496) ? W[k * 64 + o] : 0.f;
    int d1 = __float2int_rn(w * inv1);
    d1 = max(-127, min(127, d1));
    float r = w - s1 * (float)d1;
    int d2 = __float2int_rn(r * inv2);    // in [-64, 64]
    d2 = max(-127, min(127, d2));

    int ks = k >> 5, wrd = (k >> 2) & 7, tig = wrd & 3, half = wrd >> 2, byt = k & 3;
    int addr = o * COLB + ks * 32 + tig * 8 + half * 4 + byt;
    g_Wd1[addr] = (signed char)d1;
    g_Wd2[addr] = (signed char)d2;

    red[k] = w;
    __syncthreads();
    for (int d = 256; d; d >>= 1) {
        if (k < d) red[k] += red[k + d];
        __syncthreads();
    }
    if (k == 0) {
        g_corr[o] = red[0] * (1.0f / 255.0f);
        if (o == 0) g_sc = (2.0f / 255.0f) * s1 * (1.0f / 128.0f);
    }
}

// ---------------------------------------------------------------------------
// Main persistent kernel. SMEM: sA0 | sA1 | B1 | B2 | bw0 | bw1 | corr
// ---------------------------------------------------------------------------
#define SMEM_DYN (2 * ASZ + 2 * BSZ + 2 * 544 + 256)   // 206144

__device__ __forceinline__ void buildA(const uint32_t* __restrict__ bw, char* rowp,
                                       int q, int g4, uint32_t sel0, uint32_t sel1,
                                       uint32_t M1, uint32_t M2, int s)
{
    #pragma unroll
    for (int m = 0; m < 8; m++) {
        int wbase = q * 32 + m * 4;
        uint32_t A0 = bw[wbase + g4];
        uint32_t acc[4];
        #pragma unroll
        for (int j = 0; j < 4; j++) {
            uint32_t B0 = bw[wbase + g4 + j + 1];
            uint32_t X = __byte_perm(A0, B0, sel0);
            uint32_t Y = __byte_perm(A0, B0, sel1);
            acc[j] = (((X << s) & M1) | ((Y >> (8 - s)) & M2)) ^ 0x80808080u;
            A0 = B0;
        }
        *(uint4*)(rowp + m * 16) = make_uint4(acc[0], acc[1], acc[2], acc[3]);
    }
}

static __global__ void __launch_bounds__(512, 1)
bf_main(const uint32_t* __restrict__ xw, float* __restrict__ out)
{
    extern __shared__ __align__(16) char sm[];
    char* sA0 = sm;
    char* sA1 = sm + ASZ;
    char* sB1 = sm + 2 * ASZ;
    char* sB2 = sm + 2 * ASZ + BSZ;
    uint32_t* bw0 = (uint32_t*)(sm + 2 * ASZ + 2 * BSZ);
    uint32_t* bw1 = bw0 + 136;
    float* scorr  = (float*)(sm + 2 * ASZ + 2 * BSZ + 2 * 544);

    int t = threadIdx.x, lane = t & 31, wid = t >> 5;
    const int stride = g_stride;
    const float sc = g_sc;

    // ---- invariants: A build (thread -> row t>>2, quarter t&3) ----
    const int r = t >> 2, q = t & 3;
    const int g = r >> 3, s = r & 7;
    const int g4 = g >> 2, gr = g & 3;
    const uint32_t sel0 = 0x3210u + 0x1111u * (uint32_t)gr;
    const uint32_t sel1 = sel0 + 0x1111u;
    const uint32_t M1 = 0x01010101u * ((0xFFu << s) & 0xFFu);
    const uint32_t M2 = 0x01010101u * (0xFFu >> (8 - s));
    char* rowp0 = sA0 + r * COLA + q * 128;
    char* rowp1 = sA1 + r * COLA + q * 128;

    // ---- invariants: MMA (warp = 16-row m-block x 32-col n-half) ----
    const int mb = wid >> 1, nh = wid & 1;
    const int rb = mb * 16;
    const int gid = lane >> 2, tig = lane & 3;
    const int aOff = (rb + gid) * COLA + 4 * tig;
    const int colbase = nh * 32;
    const int bCol = (colbase + gid) * COLB + tig * 8;
    const int row0 = rb + gid;
    const bool early = ((wid >> 2) & 1) != 0;   // per-SMSP 2 early + 2 late warps

    const int n0 = blockIdx.x;

    // ---- prologue ----
    {
        unsigned char* b0 = (unsigned char*)bw0;
        unsigned char* b1 = (unsigned char*)bw1;
        b0[t] = (unsigned char)xw[((size_t)n0 * 512 + t) * (size_t)stride];
        int n1 = n0 + 148;                       // always < 2048 (n0 <= 147)
        b1[t] = (unsigned char)xw[((size_t)n1 * 512 + t) * (size_t)stride];
        const uint4* w1 = (const uint4*)g_Wd1;
        const uint4* w2 = (const uint4*)g_Wd2;
        uint4* p1 = (uint4*)sB1;
        uint4* p2 = (uint4*)sB2;
        for (int i = t; i < BSZ / 16; i += 512) { p1[i] = w1[i]; p2[i] = w2[i]; }
        if (t < 64) scorr[t] = g_corr[t];
        if (t < 8)  { bw0[128 + t] = 0u; bw1[128 + t] = 0u; }
    }
    // register-carried byte for tile n0+296
    uint32_t breg;
    {
        int nb = n0 + 296;
        if (nb > 2047) nb = 2047;
        breg = xw[((size_t)nb * 512 + t) * (size_t)stride];
    }
    __syncthreads();

    float corr0[4], corr1[4];
    #pragma unroll
    for (int nt = 0; nt < 4; nt++) {
        int col = colbase + nt * 8 + 2 * tig;
        corr0[nt] = scorr[col];
        corr1[nt] = scorr[col + 1];
    }

    buildA(bw0, rowp0, q, g4, sel0, sel1, M1, M2, s);
    __syncthreads();

    int p = 0;
    for (int n = n0; n < 2048; n += 148, p ^= 1) {
        const char* sA      = p ? sA1 : sA0;
        char*       rowpN   = p ? rowp0 : rowp1;        // build target sA[p^1]
        const uint32_t* bwN = p ? bw0 : bw1;            // bytes of tile n+148
        uint32_t*   bwS     = p ? bw1 : bw0;            // stale buffer -> n+296
        const bool  haveNext = (n + 148) < 2048;

        if (early && haveNext)
            buildA(bwN, rowpN, q, g4, sel0, sel1, M1, M2, s);

        // ---- MMA over both digits ----
        int c1[16], c2[16];
        #pragma unroll
        for (int i = 0; i < 16; i++) { c1[i] = 0; c2[i] = 0; }

        const char* aR = sA + aOff;
        #pragma unroll
        for (int ks = 0; ks < 16; ks++) {
            int k0 = ks * 32;
            uint32_t a0 = *(const uint32_t*)(aR + k0);
            uint32_t a2 = *(const uint32_t*)(aR + k0 + 16);
            uint32_t a1 = *(const uint32_t*)(aR + 8 * COLA + k0);
            uint32_t a3 = *(const uint32_t*)(aR + 8 * COLA + k0 + 16);
            #pragma unroll
            for (int nt = 0; nt < 4; nt++) {
                uint2 b = *(const uint2*)(sB1 + bCol + nt * (8 * COLB) + k0);
                imma(c1 + 4 * nt, a0, a1, a2, a3, b.x, b.y);
                uint2 e = *(const uint2*)(sB2 + bCol + nt * (8 * COLB) + k0);
                imma(c2 + 4 * nt, a0, a1, a2, a3, e.x, e.y);
            }
        }

        // ---- epilogue: out = sc * ((C1<<7)+C2) + corr ----
        {
            float* po = out + (size_t)n * 8192;
            #pragma unroll
            for (int nt = 0; nt < 4; nt++) {
                int col = colbase + nt * 8 + 2 * tig;
                float2 v0, v1;
                v0.x = fmaf(sc, (float)((c1[4*nt+0] << 7) + c2[4*nt+0]), corr0[nt]);
                v0.y = fmaf(sc, (float)((c1[4*nt+1] << 7) + c2[4*nt+1]), corr1[nt]);
                v1.x = fmaf(sc, (float)((c1[4*nt+2] << 7) + c2[4*nt+2]), corr0[nt]);
                v1.y = fmaf(sc, (float)((c1[4*nt+3] << 7) + c2[4*nt+3]), corr1[nt]);
                __stcs((float2*)(po + row0 * 64 + col), v0);
                __stcs((float2*)(po + (row0 + 8) * 64 + col), v1);
            }
        }

        if (!early && haveNext)
            buildA(bwN, rowpN, q, g4, sel0, sel1, M1, M2, s);

        // ---- byte pipeline: commit reg byte (n+296), fetch (n+444) ----
        ((unsigned char*)bwS)[t] = (unsigned char)breg;
        {
            int nb = n + 444;
            if (nb > 2047) nb = 2047;
            breg = xw[((size_t)nb * 512 + t) * (size_t)stride];
        }
        __syncthreads();
    }
}

// ---------------------------------------------------------------------------
extern "C" void kernel_launch(void* const* d_in, const int* in_sizes, int n_in,
                              void* d_out, int out_size)
{
    const uint32_t* xw  = (const uint32_t*)d_in[0];
    const float*    W   = (const float*)d_in[1];
    float*          out = (float*)d_out;

    cudaFuncSetAttribute(bf_main, cudaFuncAttributeMaxDynamicSharedMemorySize, SMEM_DYN);
    bf_prep<<<64, 512>>>(W, xw);
    bf_main<<<148, 512, SMEM_DYN>>>(xw, out);
}